// round 3
// baseline (speedup 1.0000x reference)
#include <cuda_runtime.h>
#include <cstdint>
#include <cstddef>

// ---------------------------------------------------------------------------
// Problem constants (fixed shapes from the reference)
// ---------------------------------------------------------------------------
#define HDIM 1024
#define IDIM 2048
#define NEXP 8
#define NTOK 4096
#define SEG  4096            // row-slots per expert segment
#define NSEG 9               // 8 routed experts + 1 shared "expert"

// Output layout (flatten-and-concat of the reference's return tuple, fp32):
//   [0, NTOK*HDIM)            routed + shared output
//   [NTOK*HDIM]               aux_loss
//   [NTOK*HDIM + 1]           z_loss
//   [NTOK*HDIM + 2, ... )     router_logits [NTOK, NEXP]
#define OUT_AUX    ((size_t)NTOK * HDIM)
#define OUT_Z      (OUT_AUX + 1)
#define OUT_LOGITS (OUT_AUX + 2)

// ---------------------------------------------------------------------------
// Static device scratch (no allocations allowed)
// ---------------------------------------------------------------------------
__device__ float g_out1[(size_t)NSEG * SEG * IDIM];   // silu(gate)*up  [rows, IDIM]
__device__ int   g_row_token[NEXP * SEG];
__device__ float g_row_weight[NEXP * SEG];
__device__ int   g_cnt[NEXP];
__device__ int   g_disp[NEXP];
__device__ float g_psum[NEXP];
__device__ float g_zsum;

// ---------------------------------------------------------------------------
// Packed f32x2 helpers (sm_100+: double-rate fp32 FMA)
// ---------------------------------------------------------------------------
__device__ __forceinline__ unsigned long long pack2s(float v) {
    unsigned long long r;
    asm("mov.b64 %0, {%1, %2};" : "=l"(r) : "f"(v), "f"(v));
    return r;
}
__device__ __forceinline__ void unpack2(unsigned long long v, float& lo, float& hi) {
    asm("mov.b64 {%0, %1}, %2;" : "=f"(lo), "=f"(hi) : "l"(v));
}
__device__ __forceinline__ unsigned long long ffma2(unsigned long long a,
                                                    unsigned long long b,
                                                    unsigned long long c) {
    unsigned long long d;
    asm("fma.rn.f32x2 %0, %1, %2, %3;" : "=l"(d) : "l"(a), "l"(b), "l"(c));
    return d;
}

// ---------------------------------------------------------------------------
// Init: zero all per-launch scratch (graph replays must be idempotent)
// ---------------------------------------------------------------------------
__global__ void init_kernel() {
    int tid = blockIdx.x * blockDim.x + threadIdx.x;
    int stride = gridDim.x * blockDim.x;
    for (int i = tid; i < NEXP * SEG; i += stride) {
        g_row_token[i] = 0;
        g_row_weight[i] = 0.0f;
    }
    if (tid < NEXP) { g_cnt[tid] = 0; g_disp[tid] = 0; g_psum[tid] = 0.0f; }
    if (tid == 0) g_zsum = 0.0f;
}

// ---------------------------------------------------------------------------
// Router: logits, softmax, top-2, row lists, loss partials
// One warp per token; router_w (1024x8 = 32KB) staged in shared.
// ---------------------------------------------------------------------------
__global__ __launch_bounds__(256) void router_kernel(
    const float* __restrict__ x, const float* __restrict__ rw,
    float* __restrict__ out)
{
    __shared__ float s_rw[HDIM * NEXP];
    int tid = threadIdx.x;
    for (int i = tid; i < HDIM * NEXP; i += 256) s_rw[i] = rw[i];
    __syncthreads();

    int warp = tid >> 5, lane = tid & 31;
    int t = blockIdx.x * 8 + warp;

    float acc[NEXP];
#pragma unroll
    for (int e = 0; e < NEXP; e++) acc[e] = 0.0f;

    const float* xr = x + (size_t)t * HDIM;
    for (int h0 = 0; h0 < HDIM; h0 += 32) {
        float xv = xr[h0 + lane];
        const float4* r = (const float4*)&s_rw[(size_t)(h0 + lane) * NEXP];
        float4 r0 = r[0], r1 = r[1];
        acc[0] += xv * r0.x; acc[1] += xv * r0.y;
        acc[2] += xv * r0.z; acc[3] += xv * r0.w;
        acc[4] += xv * r1.x; acc[5] += xv * r1.y;
        acc[6] += xv * r1.z; acc[7] += xv * r1.w;
    }
#pragma unroll
    for (int e = 0; e < NEXP; e++)
#pragma unroll
        for (int off = 16; off; off >>= 1)
            acc[e] += __shfl_xor_sync(0xffffffffu, acc[e], off);

    if (lane == 0) {
        float mx = acc[0];
#pragma unroll
        for (int e = 1; e < NEXP; e++) mx = fmaxf(mx, acc[e]);
        float p[NEXP], s = 0.0f;
#pragma unroll
        for (int e = 0; e < NEXP; e++) { p[e] = expf(acc[e] - mx); s += p[e]; }
        float inv = 1.0f / s;
#pragma unroll
        for (int e = 0; e < NEXP; e++) p[e] *= inv;

        float lse = logf(s) + mx;
        atomicAdd(&g_zsum, lse * lse);
#pragma unroll
        for (int e = 0; e < NEXP; e++) atomicAdd(&g_psum[e], p[e]);
#pragma unroll
        for (int e = 0; e < NEXP; e++)
            out[OUT_LOGITS + (size_t)t * NEXP + e] = acc[e];

        // top-2 (ties -> lower index, matching jax.lax.top_k)
        int e1 = 0;
#pragma unroll
        for (int e = 1; e < NEXP; e++) if (p[e] > p[e1]) e1 = e;
        int e2 = (e1 == 0) ? 1 : 0;
#pragma unroll
        for (int e = 0; e < NEXP; e++) if (e != e1 && p[e] > p[e2]) e2 = e;

        float ws = p[e1] + p[e2];
        float w1 = p[e1] / ws, w2 = p[e2] / ws;
        atomicAdd(&g_disp[e1], 1);
        atomicAdd(&g_disp[e2], 1);
        int p1 = atomicAdd(&g_cnt[e1], 1);
        g_row_token[e1 * SEG + p1] = t;
        g_row_weight[e1 * SEG + p1] = w1;
        int p2 = atomicAdd(&g_cnt[e2], 1);
        g_row_token[e2 * SEG + p2] = t;
        g_row_weight[e2 * SEG + p2] = w2;
    }
}

// ---------------------------------------------------------------------------
// Finalize scalars (aux_loss, z_loss)
// ---------------------------------------------------------------------------
__global__ void finalize_kernel(float* __restrict__ out) {
    if (threadIdx.x == 0 && blockIdx.x == 0) {
        float aux = 0.0f;
        for (int e = 0; e < NEXP; e++) {
            float tpe = (float)g_disp[e] / (2.0f * (float)NTOK);
            float ppe = g_psum[e] / (float)NTOK;
            aux += tpe * ppe;
        }
        out[OUT_AUX] = (float)NEXP * aux;
        out[OUT_Z] = g_zsum / (float)NTOK;
    }
}

// ---------------------------------------------------------------------------
// GEMM1: per segment, gathered rows  ->  out1 = silu(X@Gw) * (X@Uw)
// Tile: M=128, N=64 (per matrix, G and U fused), K-step 16, 256 threads.
// Thread micro-tile: 4 m-pairs (f32x2 over M) x 4 n per matrix.
// ---------------------------------------------------------------------------
__global__ __launch_bounds__(256) void gemm1_kernel(
    const float* __restrict__ x,
    const float* __restrict__ gate_w, const float* __restrict__ up_w,
    const float* __restrict__ sgw, const float* __restrict__ suw)
{
    const int seg = blockIdx.y >> 5;      // 0..8
    const int mt  = blockIdx.y & 31;
    const int base_m = mt * 128;
    const float *gw, *uw;
    if (seg < NEXP) {
        if (base_m >= g_cnt[seg]) return;
        gw = gate_w + (size_t)seg * HDIM * IDIM;
        uw = up_w   + (size_t)seg * HDIM * IDIM;
    } else {
        gw = sgw; uw = suw;
    }

    __shared__ float As[16][128];
    __shared__ float Bg[16][64];
    __shared__ float Bu[16][64];
    __shared__ int   s_tok[128];

    const int tid = threadIdx.x;
    if (tid < 128) {
        int r = base_m + tid;
        s_tok[tid] = (seg < NEXP) ? g_row_token[seg * SEG + r] : r;
    }
    __syncthreads();

    const int tx = tid & 15, ty = tid >> 4;
    unsigned long long accG[4][4], accU[4][4];
#pragma unroll
    for (int i = 0; i < 4; i++)
#pragma unroll
        for (int j = 0; j < 4; j++) { accG[i][j] = 0ull; accU[i][j] = 0ull; }

    const int la_m = tid >> 1;
    const int la_k = (tid & 1) * 8;
    const float* xrow = x + (size_t)s_tok[la_m] * HDIM + la_k;
    const int lb_k = tid >> 4;
    const int lb_n = (tid & 15) * 4;
    const int nb = blockIdx.x;
    const float* gptr = gw + (size_t)lb_k * IDIM + nb * 64 + lb_n;
    const float* uptr = uw + (size_t)lb_k * IDIM + nb * 64 + lb_n;

    for (int k0 = 0; k0 < HDIM; k0 += 16) {
        float4 a0 = *(const float4*)(xrow + k0);
        float4 a1 = *(const float4*)(xrow + k0 + 4);
        float4 bg = *(const float4*)(gptr + (size_t)k0 * IDIM);
        float4 bu = *(const float4*)(uptr + (size_t)k0 * IDIM);
        __syncthreads();
        As[la_k + 0][la_m] = a0.x; As[la_k + 1][la_m] = a0.y;
        As[la_k + 2][la_m] = a0.z; As[la_k + 3][la_m] = a0.w;
        As[la_k + 4][la_m] = a1.x; As[la_k + 5][la_m] = a1.y;
        As[la_k + 6][la_m] = a1.z; As[la_k + 7][la_m] = a1.w;
        *(float4*)&Bg[lb_k][lb_n] = bg;
        *(float4*)&Bu[lb_k][lb_n] = bu;
        __syncthreads();
#pragma unroll
        for (int kk = 0; kk < 16; kk++) {
            ulonglong2 apA = *(const ulonglong2*)&As[kk][ty * 8];
            ulonglong2 apB = *(const ulonglong2*)&As[kk][ty * 8 + 4];
            unsigned long long ap[4] = { apA.x, apA.y, apB.x, apB.y };
#pragma unroll
            for (int j = 0; j < 4; j++) {
                unsigned long long bgp = pack2s(Bg[kk][tx + j * 16]);
                unsigned long long bup = pack2s(Bu[kk][tx + j * 16]);
#pragma unroll
                for (int i = 0; i < 4; i++) {
                    accG[i][j] = ffma2(ap[i], bgp, accG[i][j]);
                    accU[i][j] = ffma2(ap[i], bup, accU[i][j]);
                }
            }
        }
    }

    // epilogue: silu(g) * u  ->  g_out1
    const size_t rbase = (size_t)seg * SEG + base_m + ty * 8;
#pragma unroll
    for (int i = 0; i < 4; i++) {
        size_t r0 = rbase + i * 2, r1 = r0 + 1;
#pragma unroll
        for (int j = 0; j < 4; j++) {
            float g0, g1, u0, u1;
            unpack2(accG[i][j], g0, g1);
            unpack2(accU[i][j], u0, u1);
            int col = nb * 64 + tx + j * 16;
            g_out1[r0 * IDIM + col] = u0 * g0 / (1.0f + expf(-g0));
            g_out1[r1 * IDIM + col] = u1 * g1 / (1.0f + expf(-g1));
        }
    }
}

// ---------------------------------------------------------------------------
// GEMM2: out1 @ down_w, weight-scaled atomic scatter into the output.
// Tile: M=128, N=128, K-step 16, 256 threads. 4 m-pairs x 8 n per thread.
// ---------------------------------------------------------------------------
__global__ __launch_bounds__(256) void gemm2_kernel(
    const float* __restrict__ down_w, const float* __restrict__ sdw,
    float* __restrict__ out)
{
    const int seg = blockIdx.y >> 5;
    const int mt  = blockIdx.y & 31;
    const int base_m = mt * 128;
    const float* bw;
    if (seg < NEXP) {
        if (base_m >= g_cnt[seg]) return;
        bw = down_w + (size_t)seg * IDIM * HDIM;
    } else {
        bw = sdw;
    }

    __shared__ float As[16][128];
    __shared__ float Bs[16][128];

    const int tid = threadIdx.x;
    const int tx = tid & 15, ty = tid >> 4;
    unsigned long long acc[4][8];
#pragma unroll
    for (int i = 0; i < 4; i++)
#pragma unroll
        for (int j = 0; j < 8; j++) acc[i][j] = 0ull;

    const int la_m = tid >> 1;
    const int la_k = (tid & 1) * 8;
    const float* arow = g_out1 + ((size_t)seg * SEG + base_m + la_m) * IDIM + la_k;
    const int lb_k = tid >> 4;
    const int lb_n = (tid & 15) * 8;
    const int nb = blockIdx.x;
    const float* bptr = bw + (size_t)lb_k * HDIM + nb * 128 + lb_n;

    for (int k0 = 0; k0 < IDIM; k0 += 16) {
        float4 a0 = *(const float4*)(arow + k0);
        float4 a1 = *(const float4*)(arow + k0 + 4);
        float4 b0 = *(const float4*)(bptr + (size_t)k0 * HDIM);
        float4 b1 = *(const float4*)(bptr + (size_t)k0 * HDIM + 4);
        __syncthreads();
        As[la_k + 0][la_m] = a0.x; As[la_k + 1][la_m] = a0.y;
        As[la_k + 2][la_m] = a0.z; As[la_k + 3][la_m] = a0.w;
        As[la_k + 4][la_m] = a1.x; As[la_k + 5][la_m] = a1.y;
        As[la_k + 6][la_m] = a1.z; As[la_k + 7][la_m] = a1.w;
        *(float4*)&Bs[lb_k][lb_n] = b0;
        *(float4*)&Bs[lb_k][lb_n + 4] = b1;
        __syncthreads();
#pragma unroll
        for (int kk = 0; kk < 16; kk++) {
            ulonglong2 apA = *(const ulonglong2*)&As[kk][ty * 8];
            ulonglong2 apB = *(const ulonglong2*)&As[kk][ty * 8 + 4];
            unsigned long long ap[4] = { apA.x, apA.y, apB.x, apB.y };
#pragma unroll
            for (int j = 0; j < 8; j++) {
                unsigned long long bp = pack2s(Bs[kk][tx + j * 16]);
#pragma unroll
                for (int i = 0; i < 4; i++)
                    acc[i][j] = ffma2(ap[i], bp, acc[i][j]);
            }
        }
    }

    // epilogue: weight-scaled scatter-add into out[token, :]
    int tok[8]; float w[8];
#pragma unroll
    for (int rr = 0; rr < 8; rr++) {
        int r = base_m + ty * 8 + rr;
        if (seg < NEXP) {
            tok[rr] = g_row_token[seg * SEG + r];
            w[rr]   = g_row_weight[seg * SEG + r];   // 0 for padded slots
        } else {
            tok[rr] = r;
            w[rr]   = 1.0f;
        }
    }
#pragma unroll
    for (int i = 0; i < 4; i++) {
#pragma unroll
        for (int j = 0; j < 8; j++) {
            float v0, v1;
            unpack2(acc[i][j], v0, v1);
            int col = nb * 128 + tx + j * 16;
            atomicAdd(out + (size_t)tok[i * 2]     * HDIM + col, w[i * 2]     * v0);
            atomicAdd(out + (size_t)tok[i * 2 + 1] * HDIM + col, w[i * 2 + 1] * v1);
        }
    }
}

// ---------------------------------------------------------------------------
// Launch
// ---------------------------------------------------------------------------
extern "C" void kernel_launch(void* const* d_in, const int* in_sizes, int n_in,
                              void* d_out, int out_size) {
    (void)in_sizes; (void)n_in; (void)out_size;
    const float* x   = (const float*)d_in[0];
    const float* rw  = (const float*)d_in[1];
    const float* gw  = (const float*)d_in[2];
    const float* uw  = (const float*)d_in[3];
    const float* dw  = (const float*)d_in[4];
    const float* sgw = (const float*)d_in[5];
    const float* suw = (const float*)d_in[6];
    const float* sdw = (const float*)d_in[7];
    float* out = (float*)d_out;

    // zero the routed-output accumulation region (d_out is poisoned)
    cudaMemsetAsync(d_out, 0, (size_t)NTOK * HDIM * sizeof(float));
    init_kernel<<<64, 256>>>();
    router_kernel<<<NTOK / 8, 256>>>(x, rw, out);
    finalize_kernel<<<1, 32>>>(out);

    dim3 g1(IDIM / 64, NSEG * 32);      // (32, 288)
    gemm1_kernel<<<g1, 256>>>(x, gw, uw, sgw, suw);

    dim3 g2(HDIM / 128, NSEG * 32);     // (8, 288)
    gemm2_kernel<<<g2, 256>>>(dw, sdw, out);
}

// round 4
// speedup vs baseline: 1.6876x; 1.6876x over previous
#include <cuda_runtime.h>
#include <cuda_bf16.h>
#include <cstdint>
#include <cstddef>

// ---------------------------------------------------------------------------
// Problem constants
// ---------------------------------------------------------------------------
#define HDIM 1024
#define IDIM 2048
#define NEXP 8
#define NTOK 4096
#define SEG  4096
#define NSEG 9               // 8 routed experts + 1 shared "expert"

#define OUT_AUX    ((size_t)NTOK * HDIM)
#define OUT_Z      (OUT_AUX + 1)
#define OUT_LOGITS (OUT_AUX + 2)

// ---------------------------------------------------------------------------
// Static device scratch
// ---------------------------------------------------------------------------
__device__ float g_out1[(size_t)NSEG * SEG * IDIM];   // silu(gate)*up, fp32
__device__ int   g_row_token[NEXP * SEG];
__device__ float g_row_weight[NEXP * SEG];
__device__ int   g_cnt[NEXP];
__device__ int   g_disp[NEXP];
__device__ float g_psum[NEXP];
__device__ float g_zsum;

// ---------------------------------------------------------------------------
// MMA helpers (m16n8k16 bf16, fp32 accumulate)
// ---------------------------------------------------------------------------
__device__ __forceinline__ uint32_t smaddr(const void* p) {
    return (uint32_t)__cvta_generic_to_shared(p);
}
__device__ __forceinline__ void ldsm4(uint32_t r[4], uint32_t a) {
    asm volatile("ldmatrix.sync.aligned.m8n8.x4.shared.b16 {%0,%1,%2,%3},[%4];"
        : "=r"(r[0]), "=r"(r[1]), "=r"(r[2]), "=r"(r[3]) : "r"(a));
}
__device__ __forceinline__ void ldsm4t(uint32_t r[4], uint32_t a) {
    asm volatile("ldmatrix.sync.aligned.m8n8.x4.trans.shared.b16 {%0,%1,%2,%3},[%4];"
        : "=r"(r[0]), "=r"(r[1]), "=r"(r[2]), "=r"(r[3]) : "r"(a));
}
__device__ __forceinline__ void mma_bf16(float c[4], const uint32_t a[4],
                                         const uint32_t b[2]) {
    asm volatile(
        "mma.sync.aligned.m16n8k16.row.col.f32.bf16.bf16.f32 "
        "{%0,%1,%2,%3},{%4,%5,%6,%7},{%8,%9},{%0,%1,%2,%3};"
        : "+f"(c[0]), "+f"(c[1]), "+f"(c[2]), "+f"(c[3])
        : "r"(a[0]), "r"(a[1]), "r"(a[2]), "r"(a[3]), "r"(b[0]), "r"(b[1]));
}
// split fp32 pair -> packed bf16x2 (hi) + packed bf16x2 (lo residual)
__device__ __forceinline__ void split2(float x, float y, uint32_t& hi, uint32_t& lo) {
    __nv_bfloat16 hx = __float2bfloat16(x), hy = __float2bfloat16(y);
    __nv_bfloat16 lx = __float2bfloat16(x - __bfloat162float(hx));
    __nv_bfloat16 ly = __float2bfloat16(y - __bfloat162float(hy));
    hi = (uint32_t)__bfloat16_as_ushort(hx) | ((uint32_t)__bfloat16_as_ushort(hy) << 16);
    lo = (uint32_t)__bfloat16_as_ushort(lx) | ((uint32_t)__bfloat16_as_ushort(ly) << 16);
}

// ---------------------------------------------------------------------------
// Init
// ---------------------------------------------------------------------------
__global__ void init_kernel() {
    int tid = blockIdx.x * blockDim.x + threadIdx.x;
    int stride = gridDim.x * blockDim.x;
    for (int i = tid; i < NEXP * SEG; i += stride) {
        g_row_token[i] = 0;
        g_row_weight[i] = 0.0f;
    }
    if (tid < NEXP) { g_cnt[tid] = 0; g_disp[tid] = 0; g_psum[tid] = 0.0f; }
    if (tid == 0) g_zsum = 0.0f;
}

// ---------------------------------------------------------------------------
// Router (unchanged from R2 — passed at 1e-6)
// ---------------------------------------------------------------------------
__global__ __launch_bounds__(256) void router_kernel(
    const float* __restrict__ x, const float* __restrict__ rw,
    float* __restrict__ out)
{
    __shared__ float s_rw[HDIM * NEXP];
    int tid = threadIdx.x;
    for (int i = tid; i < HDIM * NEXP; i += 256) s_rw[i] = rw[i];
    __syncthreads();

    int warp = tid >> 5, lane = tid & 31;
    int t = blockIdx.x * 8 + warp;

    float acc[NEXP];
#pragma unroll
    for (int e = 0; e < NEXP; e++) acc[e] = 0.0f;

    const float* xr = x + (size_t)t * HDIM;
    for (int h0 = 0; h0 < HDIM; h0 += 32) {
        float xv = xr[h0 + lane];
        const float4* r = (const float4*)&s_rw[(size_t)(h0 + lane) * NEXP];
        float4 r0 = r[0], r1 = r[1];
        acc[0] += xv * r0.x; acc[1] += xv * r0.y;
        acc[2] += xv * r0.z; acc[3] += xv * r0.w;
        acc[4] += xv * r1.x; acc[5] += xv * r1.y;
        acc[6] += xv * r1.z; acc[7] += xv * r1.w;
    }
#pragma unroll
    for (int e = 0; e < NEXP; e++)
#pragma unroll
        for (int off = 16; off; off >>= 1)
            acc[e] += __shfl_xor_sync(0xffffffffu, acc[e], off);

    if (lane == 0) {
        float mx = acc[0];
#pragma unroll
        for (int e = 1; e < NEXP; e++) mx = fmaxf(mx, acc[e]);
        float p[NEXP], s = 0.0f;
#pragma unroll
        for (int e = 0; e < NEXP; e++) { p[e] = expf(acc[e] - mx); s += p[e]; }
        float inv = 1.0f / s;
#pragma unroll
        for (int e = 0; e < NEXP; e++) p[e] *= inv;

        float lse = logf(s) + mx;
        atomicAdd(&g_zsum, lse * lse);
#pragma unroll
        for (int e = 0; e < NEXP; e++) atomicAdd(&g_psum[e], p[e]);
#pragma unroll
        for (int e = 0; e < NEXP; e++)
            out[OUT_LOGITS + (size_t)t * NEXP + e] = acc[e];

        int e1 = 0;
#pragma unroll
        for (int e = 1; e < NEXP; e++) if (p[e] > p[e1]) e1 = e;
        int e2 = (e1 == 0) ? 1 : 0;
#pragma unroll
        for (int e = 0; e < NEXP; e++) if (e != e1 && p[e] > p[e2]) e2 = e;

        float ws = p[e1] + p[e2];
        float w1 = p[e1] / ws, w2 = p[e2] / ws;
        atomicAdd(&g_disp[e1], 1);
        atomicAdd(&g_disp[e2], 1);
        int p1 = atomicAdd(&g_cnt[e1], 1);
        g_row_token[e1 * SEG + p1] = t;
        g_row_weight[e1 * SEG + p1] = w1;
        int p2 = atomicAdd(&g_cnt[e2], 1);
        g_row_token[e2 * SEG + p2] = t;
        g_row_weight[e2 * SEG + p2] = w2;
    }
}

__global__ void finalize_kernel(float* __restrict__ out) {
    if (threadIdx.x == 0 && blockIdx.x == 0) {
        float aux = 0.0f;
        for (int e = 0; e < NEXP; e++) {
            float tpe = (float)g_disp[e] / (2.0f * (float)NTOK);
            float ppe = g_psum[e] / (float)NTOK;
            aux += tpe * ppe;
        }
        out[OUT_AUX] = (float)NEXP * aux;
        out[OUT_Z] = g_zsum / (float)NTOK;
    }
}

// ---------------------------------------------------------------------------
// GEMM1: gathered rows -> silu(X@Gw) * (X@Uw) via bf16x3 mma.sync
// Block: 128 rows x (64 gate cols + 64 up cols). 8 warps, warp tile 32x64.
// ---------------------------------------------------------------------------
__global__ __launch_bounds__(256, 1) void gemm1_kernel(
    const float* __restrict__ x,
    const float* __restrict__ gate_w, const float* __restrict__ up_w,
    const float* __restrict__ sgw, const float* __restrict__ suw)
{
    const int seg = blockIdx.y >> 5;
    const int base_m = (blockIdx.y & 31) * 128;
    const float *gw, *uw;
    if (seg < NEXP) {
        if (base_m >= g_cnt[seg]) return;
        gw = gate_w + (size_t)seg * HDIM * IDIM;
        uw = up_w   + (size_t)seg * HDIM * IDIM;
    } else { gw = sgw; uw = suw; }

    __shared__ alignas(16) __nv_bfloat16 Ah[128][24];
    __shared__ alignas(16) __nv_bfloat16 Al[128][24];
    __shared__ alignas(16) __nv_bfloat16 Bh[16][136];   // cols 0-63 gate, 64-127 up
    __shared__ alignas(16) __nv_bfloat16 Bl[16][136];
    __shared__ int s_tok[128];

    const int tid = threadIdx.x;
    const int lane = tid & 31, wid = tid >> 5;
    const int wm = wid & 3, wn = wid >> 2;
    const int nb = blockIdx.x;

    if (tid < 128)
        s_tok[tid] = (seg < NEXP) ? g_row_token[seg * SEG + base_m + tid]
                                  : (base_m + tid);
    __syncthreads();

    const int am = tid >> 1, ak = (tid & 1) * 8;
    const float* ap = x + (size_t)s_tok[am] * HDIM + ak;
    const int brow = tid >> 4, bc4 = (tid & 15) * 4;
    const float* gp = gw + (size_t)brow * IDIM + nb * 64 + bc4;
    const float* upp = uw + (size_t)brow * IDIM + nb * 64 + bc4;

    float acc[2][8][4];
#pragma unroll
    for (int i = 0; i < 2; i++)
#pragma unroll
        for (int j = 0; j < 8; j++)
#pragma unroll
            for (int q = 0; q < 4; q++) acc[i][j][q] = 0.0f;

    float4 a0 = *(const float4*)(ap);
    float4 a1 = *(const float4*)(ap + 4);
    float4 gg = *(const float4*)(gp);
    float4 uu = *(const float4*)(upp);

    for (int k0 = 0; k0 < HDIM; k0 += 16) {
        uint32_t h0, l0, h1, l1, h2, l2, h3, l3;
        split2(a0.x, a0.y, h0, l0); split2(a0.z, a0.w, h1, l1);
        split2(a1.x, a1.y, h2, l2); split2(a1.z, a1.w, h3, l3);
        *(uint4*)&Ah[am][ak] = make_uint4(h0, h1, h2, h3);
        *(uint4*)&Al[am][ak] = make_uint4(l0, l1, l2, l3);
        uint32_t gh0, gl0, gh1, gl1, uh0, ul0, uh1, ul1;
        split2(gg.x, gg.y, gh0, gl0); split2(gg.z, gg.w, gh1, gl1);
        split2(uu.x, uu.y, uh0, ul0); split2(uu.z, uu.w, uh1, ul1);
        *(uint2*)&Bh[brow][bc4]      = make_uint2(gh0, gh1);
        *(uint2*)&Bl[brow][bc4]      = make_uint2(gl0, gl1);
        *(uint2*)&Bh[brow][64 + bc4] = make_uint2(uh0, uh1);
        *(uint2*)&Bl[brow][64 + bc4] = make_uint2(ul0, ul1);
        __syncthreads();

        if (k0 + 16 < HDIM) {   // prefetch next chunk under the MMAs
            a0 = *(const float4*)(ap + k0 + 16);
            a1 = *(const float4*)(ap + k0 + 20);
            gg = *(const float4*)(gp + (size_t)(k0 + 16) * IDIM);
            uu = *(const float4*)(upp + (size_t)(k0 + 16) * IDIM);
        }

        uint32_t ah[2][4], al[2][4];
#pragma unroll
        for (int mt = 0; mt < 2; mt++) {
            int r = wm * 32 + mt * 16 + (lane & 15);
            int c = (lane >> 4) * 8;
            ldsm4(ah[mt], smaddr(&Ah[r][c]));
            ldsm4(al[mt], smaddr(&Al[r][c]));
        }
#pragma unroll
        for (int g = 0; g < 4; g++) {
            int n0 = ((g & 2) ? 64 : 0) + wn * 32 + (g & 1) * 16;
            int bc = n0 + (lane >> 4) * 8;
            int brr = lane & 15;
            uint32_t bh[4], bl[4];
            ldsm4t(bh, smaddr(&Bh[brr][bc]));
            ldsm4t(bl, smaddr(&Bl[brr][bc]));
            int j = g * 2;
#pragma unroll
            for (int mt = 0; mt < 2; mt++) {
                mma_bf16(acc[mt][j],     ah[mt], bh);
                mma_bf16(acc[mt][j],     ah[mt], bl);
                mma_bf16(acc[mt][j],     al[mt], bh);
                mma_bf16(acc[mt][j + 1], ah[mt], bh + 2);
                mma_bf16(acc[mt][j + 1], ah[mt], bl + 2);
                mma_bf16(acc[mt][j + 1], al[mt], bh + 2);
            }
        }
        __syncthreads();
    }

    // epilogue: silu(gate) * up -> g_out1 (acc j 0-3 gate, 4-7 up, same cols)
#pragma unroll
    for (int mt = 0; mt < 2; mt++) {
        int r0 = base_m + wm * 32 + mt * 16 + (lane >> 2);
        size_t row0 = (size_t)seg * SEG + r0;
        size_t row1 = row0 + 8;
#pragma unroll
        for (int jg = 0; jg < 4; jg++) {
            float* G = acc[mt][jg];
            float* U = acc[mt][4 + jg];
            int col = nb * 64 + wn * 32 + jg * 8 + (lane & 3) * 2;
            float o0 = U[0] * G[0] / (1.0f + expf(-G[0]));
            float o1 = U[1] * G[1] / (1.0f + expf(-G[1]));
            float o2 = U[2] * G[2] / (1.0f + expf(-G[2]));
            float o3 = U[3] * G[3] / (1.0f + expf(-G[3]));
            *(float2*)&g_out1[row0 * IDIM + col] = make_float2(o0, o1);
            *(float2*)&g_out1[row1 * IDIM + col] = make_float2(o2, o3);
        }
    }
}

// ---------------------------------------------------------------------------
// GEMM2: g_out1 @ down_w, weight-scaled atomic scatter. Same tiling.
// ---------------------------------------------------------------------------
__global__ __launch_bounds__(256, 1) void gemm2_kernel(
    const float* __restrict__ down_w, const float* __restrict__ sdw,
    float* __restrict__ out)
{
    const int seg = blockIdx.y >> 5;
    const int base_m = (blockIdx.y & 31) * 128;
    const float* bw;
    if (seg < NEXP) {
        if (base_m >= g_cnt[seg]) return;
        bw = down_w + (size_t)seg * IDIM * HDIM;
    } else bw = sdw;

    __shared__ alignas(16) __nv_bfloat16 Ah[128][24];
    __shared__ alignas(16) __nv_bfloat16 Al[128][24];
    __shared__ alignas(16) __nv_bfloat16 Bh[16][136];
    __shared__ alignas(16) __nv_bfloat16 Bl[16][136];
    __shared__ int   s_tok[128];
    __shared__ float s_w[128];

    const int tid = threadIdx.x;
    const int lane = tid & 31, wid = tid >> 5;
    const int wm = wid & 3, wn = wid >> 2;
    const int nb = blockIdx.x;

    if (tid < 128) {
        if (seg < NEXP) {
            s_tok[tid] = g_row_token[seg * SEG + base_m + tid];
            s_w[tid]   = g_row_weight[seg * SEG + base_m + tid];
        } else { s_tok[tid] = base_m + tid; s_w[tid] = 1.0f; }
    }
    __syncthreads();

    const int am = tid >> 1, ak = (tid & 1) * 8;
    const float* ap = g_out1 + ((size_t)seg * SEG + base_m + am) * IDIM + ak;
    const int brow = tid >> 4, bc8 = (tid & 15) * 8;
    const float* bp = bw + (size_t)brow * HDIM + nb * 128 + bc8;

    float acc[2][8][4];
#pragma unroll
    for (int i = 0; i < 2; i++)
#pragma unroll
        for (int j = 0; j < 8; j++)
#pragma unroll
            for (int q = 0; q < 4; q++) acc[i][j][q] = 0.0f;

    float4 a0 = *(const float4*)(ap);
    float4 a1 = *(const float4*)(ap + 4);
    float4 b0 = *(const float4*)(bp);
    float4 b1 = *(const float4*)(bp + 4);

    for (int k0 = 0; k0 < IDIM; k0 += 16) {
        uint32_t h0, l0, h1, l1, h2, l2, h3, l3;
        split2(a0.x, a0.y, h0, l0); split2(a0.z, a0.w, h1, l1);
        split2(a1.x, a1.y, h2, l2); split2(a1.z, a1.w, h3, l3);
        *(uint4*)&Ah[am][ak] = make_uint4(h0, h1, h2, h3);
        *(uint4*)&Al[am][ak] = make_uint4(l0, l1, l2, l3);
        uint32_t p0, q0, p1, q1, p2, q2, p3, q3;
        split2(b0.x, b0.y, p0, q0); split2(b0.z, b0.w, p1, q1);
        split2(b1.x, b1.y, p2, q2); split2(b1.z, b1.w, p3, q3);
        *(uint4*)&Bh[brow][bc8] = make_uint4(p0, p1, p2, p3);
        *(uint4*)&Bl[brow][bc8] = make_uint4(q0, q1, q2, q3);
        __syncthreads();

        if (k0 + 16 < IDIM) {
            a0 = *(const float4*)(ap + k0 + 16);
            a1 = *(const float4*)(ap + k0 + 20);
            b0 = *(const float4*)(bp + (size_t)(k0 + 16) * HDIM);
            b1 = *(const float4*)(bp + (size_t)(k0 + 16) * HDIM + 4);
        }

        uint32_t ah[2][4], al[2][4];
#pragma unroll
        for (int mt = 0; mt < 2; mt++) {
            int r = wm * 32 + mt * 16 + (lane & 15);
            int c = (lane >> 4) * 8;
            ldsm4(ah[mt], smaddr(&Ah[r][c]));
            ldsm4(al[mt], smaddr(&Al[r][c]));
        }
#pragma unroll
        for (int g = 0; g < 4; g++) {
            int n0 = wn * 64 + g * 16;
            int bc = n0 + (lane >> 4) * 8;
            int brr = lane & 15;
            uint32_t bh[4], bl[4];
            ldsm4t(bh, smaddr(&Bh[brr][bc]));
            ldsm4t(bl, smaddr(&Bl[brr][bc]));
            int j = g * 2;
#pragma unroll
            for (int mt = 0; mt < 2; mt++) {
                mma_bf16(acc[mt][j],     ah[mt], bh);
                mma_bf16(acc[mt][j],     ah[mt], bl);
                mma_bf16(acc[mt][j],     al[mt], bh);
                mma_bf16(acc[mt][j + 1], ah[mt], bh + 2);
                mma_bf16(acc[mt][j + 1], ah[mt], bl + 2);
                mma_bf16(acc[mt][j + 1], al[mt], bh + 2);
            }
        }
        __syncthreads();
    }

    // epilogue: weight-scaled scatter-add
#pragma unroll
    for (int mt = 0; mt < 2; mt++) {
        int rl0 = wm * 32 + mt * 16 + (lane >> 2);
        int t0 = s_tok[rl0], t1 = s_tok[rl0 + 8];
        float w0 = s_w[rl0], w1 = s_w[rl0 + 8];
#pragma unroll
        for (int j = 0; j < 8; j++) {
            float* C = acc[mt][j];
            int col = nb * 128 + wn * 64 + j * 8 + (lane & 3) * 2;
            atomicAdd(&out[(size_t)t0 * HDIM + col],     w0 * C[0]);
            atomicAdd(&out[(size_t)t0 * HDIM + col + 1], w0 * C[1]);
            atomicAdd(&out[(size_t)t1 * HDIM + col],     w1 * C[2]);
            atomicAdd(&out[(size_t)t1 * HDIM + col + 1], w1 * C[3]);
        }
    }
}

// ---------------------------------------------------------------------------
// Launch
// ---------------------------------------------------------------------------
extern "C" void kernel_launch(void* const* d_in, const int* in_sizes, int n_in,
                              void* d_out, int out_size) {
    (void)in_sizes; (void)n_in; (void)out_size;
    const float* x   = (const float*)d_in[0];
    const float* rw  = (const float*)d_in[1];
    const float* gw  = (const float*)d_in[2];
    const float* uw  = (const float*)d_in[3];
    const float* dw  = (const float*)d_in[4];
    const float* sgw = (const float*)d_in[5];
    const float* suw = (const float*)d_in[6];
    const float* sdw = (const float*)d_in[7];
    float* out = (float*)d_out;

    cudaMemsetAsync(d_out, 0, (size_t)NTOK * HDIM * sizeof(float));
    init_kernel<<<64, 256>>>();
    router_kernel<<<NTOK / 8, 256>>>(x, rw, out);
    finalize_kernel<<<1, 32>>>(out);

    dim3 g1(IDIM / 64, NSEG * 32);      // (32, 288)
    gemm1_kernel<<<g1, 256>>>(x, gw, uw, sgw, suw);

    dim3 g2(HDIM / 128, NSEG * 32);     // (8, 288)
    gemm2_kernel<<<g2, 256>>>(dw, sdw, out);
}

// round 5
// speedup vs baseline: 2.5040x; 1.4837x over previous
#include <cuda_runtime.h>
#include <cuda_bf16.h>
#include <cstdint>
#include <cstddef>

// ---------------------------------------------------------------------------
// Problem constants
// ---------------------------------------------------------------------------
#define HDIM 1024
#define IDIM 2048
#define NEXP 8
#define NTOK 4096
#define SEG  4096
#define NSEG 9               // 8 routed experts + 1 shared "expert"
#define STAGES 4

#define OUT_AUX    ((size_t)NTOK * HDIM)
#define OUT_Z      (OUT_AUX + 1)
#define OUT_LOGITS (OUT_AUX + 2)

// ---------------------------------------------------------------------------
// Static device scratch
// ---------------------------------------------------------------------------
__device__ int   g_row_token[NEXP * SEG];
__device__ float g_row_weight[NEXP * SEG];
__device__ int   g_cnt[NEXP];
__device__ int   g_disp[NEXP];
__device__ float g_psum[NEXP];
__device__ float g_zsum;

// bf16 hi/lo split copies of all GEMM operands (converted once per launch)
__device__ __nv_bfloat16 g_xh[(size_t)NTOK * HDIM];
__device__ __nv_bfloat16 g_xl[(size_t)NTOK * HDIM];
__device__ __nv_bfloat16 g_gwh[(size_t)NEXP * HDIM * IDIM];
__device__ __nv_bfloat16 g_gwl[(size_t)NEXP * HDIM * IDIM];
__device__ __nv_bfloat16 g_uwh[(size_t)NEXP * HDIM * IDIM];
__device__ __nv_bfloat16 g_uwl[(size_t)NEXP * HDIM * IDIM];
__device__ __nv_bfloat16 g_dwh[(size_t)NEXP * IDIM * HDIM];
__device__ __nv_bfloat16 g_dwl[(size_t)NEXP * IDIM * HDIM];
__device__ __nv_bfloat16 g_sgwh[(size_t)HDIM * IDIM];
__device__ __nv_bfloat16 g_sgwl[(size_t)HDIM * IDIM];
__device__ __nv_bfloat16 g_suwh[(size_t)HDIM * IDIM];
__device__ __nv_bfloat16 g_suwl[(size_t)HDIM * IDIM];
__device__ __nv_bfloat16 g_sdwh[(size_t)IDIM * HDIM];
__device__ __nv_bfloat16 g_sdwl[(size_t)IDIM * HDIM];
__device__ __nv_bfloat16 g_o1h[(size_t)NSEG * SEG * IDIM];
__device__ __nv_bfloat16 g_o1l[(size_t)NSEG * SEG * IDIM];

// ---------------------------------------------------------------------------
// Helpers
// ---------------------------------------------------------------------------
__device__ __forceinline__ uint32_t smaddr(const void* p) {
    return (uint32_t)__cvta_generic_to_shared(p);
}
__device__ __forceinline__ void ldsm4(uint32_t r[4], uint32_t a) {
    asm volatile("ldmatrix.sync.aligned.m8n8.x4.shared.b16 {%0,%1,%2,%3},[%4];"
        : "=r"(r[0]), "=r"(r[1]), "=r"(r[2]), "=r"(r[3]) : "r"(a));
}
__device__ __forceinline__ void ldsm4t(uint32_t r[4], uint32_t a) {
    asm volatile("ldmatrix.sync.aligned.m8n8.x4.trans.shared.b16 {%0,%1,%2,%3},[%4];"
        : "=r"(r[0]), "=r"(r[1]), "=r"(r[2]), "=r"(r[3]) : "r"(a));
}
__device__ __forceinline__ void mma_bf16(float c[4], const uint32_t a[4],
                                         const uint32_t b[2]) {
    asm volatile(
        "mma.sync.aligned.m16n8k16.row.col.f32.bf16.bf16.f32 "
        "{%0,%1,%2,%3},{%4,%5,%6,%7},{%8,%9},{%0,%1,%2,%3};"
        : "+f"(c[0]), "+f"(c[1]), "+f"(c[2]), "+f"(c[3])
        : "r"(a[0]), "r"(a[1]), "r"(a[2]), "r"(a[3]), "r"(b[0]), "r"(b[1]));
}
__device__ __forceinline__ void split2(float x, float y, uint32_t& hi, uint32_t& lo) {
    __nv_bfloat16 hx = __float2bfloat16(x), hy = __float2bfloat16(y);
    __nv_bfloat16 lx = __float2bfloat16(x - __bfloat162float(hx));
    __nv_bfloat16 ly = __float2bfloat16(y - __bfloat162float(hy));
    hi = (uint32_t)__bfloat16_as_ushort(hx) | ((uint32_t)__bfloat16_as_ushort(hy) << 16);
    lo = (uint32_t)__bfloat16_as_ushort(lx) | ((uint32_t)__bfloat16_as_ushort(ly) << 16);
}
__device__ __forceinline__ void cp16(void* dst, const void* src) {
    asm volatile("cp.async.cg.shared.global [%0],[%1],16;"
        :: "r"(smaddr(dst)), "l"(src));
}
__device__ __forceinline__ void cp_commit() {
    asm volatile("cp.async.commit_group;");
}
template <int N> __device__ __forceinline__ void cp_wait() {
    asm volatile("cp.async.wait_group %0;" :: "n"(N));
}

// ---------------------------------------------------------------------------
// Init
// ---------------------------------------------------------------------------
__global__ void init_kernel() {
    int tid = blockIdx.x * blockDim.x + threadIdx.x;
    int stride = gridDim.x * blockDim.x;
    for (int i = tid; i < NEXP * SEG; i += stride) {
        g_row_token[i] = 0;
        g_row_weight[i] = 0.0f;
    }
    if (tid < NEXP) { g_cnt[tid] = 0; g_disp[tid] = 0; g_psum[tid] = 0.0f; }
    if (tid == 0) g_zsum = 0.0f;
}

// ---------------------------------------------------------------------------
// fp32 -> bf16 hi/lo split conversion for all operands. blockIdx.y = tensor.
// ---------------------------------------------------------------------------
__global__ __launch_bounds__(256) void convert_kernel(
    const float* __restrict__ x, const float* __restrict__ gw,
    const float* __restrict__ uw, const float* __restrict__ dw,
    const float* __restrict__ sgw, const float* __restrict__ suw,
    const float* __restrict__ sdw)
{
    const float* src; __nv_bfloat16 *dh, *dl; size_t n;
    switch (blockIdx.y) {
        case 0: src = x;   dh = g_xh;   dl = g_xl;   n = (size_t)NTOK * HDIM; break;
        case 1: src = gw;  dh = g_gwh;  dl = g_gwl;  n = (size_t)NEXP * HDIM * IDIM; break;
        case 2: src = uw;  dh = g_uwh;  dl = g_uwl;  n = (size_t)NEXP * HDIM * IDIM; break;
        case 3: src = dw;  dh = g_dwh;  dl = g_dwl;  n = (size_t)NEXP * IDIM * HDIM; break;
        case 4: src = sgw; dh = g_sgwh; dl = g_sgwl; n = (size_t)HDIM * IDIM; break;
        case 5: src = suw; dh = g_suwh; dl = g_suwl; n = (size_t)HDIM * IDIM; break;
        default: src = sdw; dh = g_sdwh; dl = g_sdwl; n = (size_t)IDIM * HDIM; break;
    }
    size_t n4 = n >> 2;
    size_t stride = (size_t)gridDim.x * blockDim.x;
    for (size_t i = (size_t)blockIdx.x * blockDim.x + threadIdx.x; i < n4; i += stride) {
        float4 v = ((const float4*)src)[i];
        uint32_t h0, l0, h1, l1;
        split2(v.x, v.y, h0, l0);
        split2(v.z, v.w, h1, l1);
        ((uint2*)dh)[i] = make_uint2(h0, h1);
        ((uint2*)dl)[i] = make_uint2(l0, l1);
    }
}

// ---------------------------------------------------------------------------
// Router (unchanged — validated at 1e-6)
// ---------------------------------------------------------------------------
__global__ __launch_bounds__(256) void router_kernel(
    const float* __restrict__ x, const float* __restrict__ rw,
    float* __restrict__ out)
{
    __shared__ float s_rw[HDIM * NEXP];
    int tid = threadIdx.x;
    for (int i = tid; i < HDIM * NEXP; i += 256) s_rw[i] = rw[i];
    __syncthreads();

    int warp = tid >> 5, lane = tid & 31;
    int t = blockIdx.x * 8 + warp;

    float acc[NEXP];
#pragma unroll
    for (int e = 0; e < NEXP; e++) acc[e] = 0.0f;

    const float* xr = x + (size_t)t * HDIM;
    for (int h0 = 0; h0 < HDIM; h0 += 32) {
        float xv = xr[h0 + lane];
        const float4* r = (const float4*)&s_rw[(size_t)(h0 + lane) * NEXP];
        float4 r0 = r[0], r1 = r[1];
        acc[0] += xv * r0.x; acc[1] += xv * r0.y;
        acc[2] += xv * r0.z; acc[3] += xv * r0.w;
        acc[4] += xv * r1.x; acc[5] += xv * r1.y;
        acc[6] += xv * r1.z; acc[7] += xv * r1.w;
    }
#pragma unroll
    for (int e = 0; e < NEXP; e++)
#pragma unroll
        for (int off = 16; off; off >>= 1)
            acc[e] += __shfl_xor_sync(0xffffffffu, acc[e], off);

    if (lane == 0) {
        float mx = acc[0];
#pragma unroll
        for (int e = 1; e < NEXP; e++) mx = fmaxf(mx, acc[e]);
        float p[NEXP], s = 0.0f;
#pragma unroll
        for (int e = 0; e < NEXP; e++) { p[e] = expf(acc[e] - mx); s += p[e]; }
        float inv = 1.0f / s;
#pragma unroll
        for (int e = 0; e < NEXP; e++) p[e] *= inv;

        float lse = logf(s) + mx;
        atomicAdd(&g_zsum, lse * lse);
#pragma unroll
        for (int e = 0; e < NEXP; e++) atomicAdd(&g_psum[e], p[e]);
#pragma unroll
        for (int e = 0; e < NEXP; e++)
            out[OUT_LOGITS + (size_t)t * NEXP + e] = acc[e];

        int e1 = 0;
#pragma unroll
        for (int e = 1; e < NEXP; e++) if (p[e] > p[e1]) e1 = e;
        int e2 = (e1 == 0) ? 1 : 0;
#pragma unroll
        for (int e = 0; e < NEXP; e++) if (e != e1 && p[e] > p[e2]) e2 = e;

        float ws = p[e1] + p[e2];
        float w1 = p[e1] / ws, w2 = p[e2] / ws;
        atomicAdd(&g_disp[e1], 1);
        atomicAdd(&g_disp[e2], 1);
        int p1 = atomicAdd(&g_cnt[e1], 1);
        g_row_token[e1 * SEG + p1] = t;
        g_row_weight[e1 * SEG + p1] = w1;
        int p2 = atomicAdd(&g_cnt[e2], 1);
        g_row_token[e2 * SEG + p2] = t;
        g_row_weight[e2 * SEG + p2] = w2;
    }
}

__global__ void finalize_kernel(float* __restrict__ out) {
    if (threadIdx.x == 0 && blockIdx.x == 0) {
        float aux = 0.0f;
        for (int e = 0; e < NEXP; e++) {
            float tpe = (float)g_disp[e] / (2.0f * (float)NTOK);
            float ppe = g_psum[e] / (float)NTOK;
            aux += tpe * ppe;
        }
        out[OUT_AUX] = (float)NEXP * aux;
        out[OUT_Z] = g_zsum / (float)NTOK;
    }
}

// ---------------------------------------------------------------------------
// Shared-memory stage structs (dynamic smem, 4 stages)
// ---------------------------------------------------------------------------
struct alignas(16) G1Smem {
    __nv_bfloat16 Ah[STAGES][128][24];
    __nv_bfloat16 Al[STAGES][128][24];
    __nv_bfloat16 Bh[STAGES][16][136];   // cols 0-63 gate, 64-127 up
    __nv_bfloat16 Bl[STAGES][16][136];
    int tok[128];
};
struct alignas(16) G2Smem {
    __nv_bfloat16 Ah[STAGES][128][24];
    __nv_bfloat16 Al[STAGES][128][24];
    __nv_bfloat16 Bh[STAGES][16][136];
    __nv_bfloat16 Bl[STAGES][16][136];
    int   tok[128];
    float w[128];
};

// ---------------------------------------------------------------------------
// GEMM1: gathered rows -> silu(X@Gw) * (X@Uw), bf16x3, cp.async 4-stage.
// Block 128 x (64 gate + 64 up), 8 warps, warp tile 32x64.
// ---------------------------------------------------------------------------
__global__ __launch_bounds__(256, 2) void gemm1_kernel()
{
    const int seg = blockIdx.y >> 5;
    const int base_m = (blockIdx.y & 31) * 128;
    const __nv_bfloat16 *gwh, *gwl, *uwh, *uwl;
    if (seg < NEXP) {
        if (base_m >= g_cnt[seg]) return;
        size_t off = (size_t)seg * HDIM * IDIM;
        gwh = g_gwh + off; gwl = g_gwl + off;
        uwh = g_uwh + off; uwl = g_uwl + off;
    } else {
        gwh = g_sgwh; gwl = g_sgwl; uwh = g_suwh; uwl = g_suwl;
    }

    extern __shared__ char smem_raw[];
    G1Smem& S = *(G1Smem*)smem_raw;

    const int tid = threadIdx.x;
    const int lane = tid & 31, wid = tid >> 5;
    const int wm = wid & 3, wn = wid >> 2;
    const int nb = blockIdx.x;

    if (tid < 128)
        S.tok[tid] = (seg < NEXP) ? g_row_token[seg * SEG + base_m + tid]
                                  : (base_m + tid);
    __syncthreads();

    // per-thread cp.async source pointers
    const int am = tid >> 1, ac = (tid & 1) * 8;
    const size_t arow = (size_t)S.tok[am] * HDIM + ac;
    const __nv_bfloat16* aSrcH = g_xh + arow;
    const __nv_bfloat16* aSrcL = g_xl + arow;
    const int brow = tid >> 4, bcol = (tid & 15) * 8;
    const __nv_bfloat16 *bSrcH, *bSrcL;
    {
        size_t boff = (size_t)brow * IDIM + nb * 64;
        if (bcol < 64) { bSrcH = gwh + boff + bcol;      bSrcL = gwl + boff + bcol; }
        else           { bSrcH = uwh + boff + bcol - 64; bSrcL = uwl + boff + bcol - 64; }
    }

    float acc[2][8][4];
#pragma unroll
    for (int i = 0; i < 2; i++)
#pragma unroll
        for (int j = 0; j < 8; j++)
#pragma unroll
            for (int q = 0; q < 4; q++) acc[i][j][q] = 0.0f;

    const int KSTEPS = HDIM / 16;   // 64
#pragma unroll 1
    for (int s = 0; s < STAGES - 1; s++) {
        int k0 = s * 16;
        cp16(&S.Ah[s][am][ac], aSrcH + k0);
        cp16(&S.Al[s][am][ac], aSrcL + k0);
        cp16(&S.Bh[s][brow][bcol], bSrcH + (size_t)k0 * IDIM);
        cp16(&S.Bl[s][brow][bcol], bSrcL + (size_t)k0 * IDIM);
        cp_commit();
    }

#pragma unroll 1
    for (int kt = 0; kt < KSTEPS; kt++) {
        cp_wait<STAGES - 2>();
        __syncthreads();

        int kn = kt + STAGES - 1;
        if (kn < KSTEPS) {
            int sn = kn & (STAGES - 1);
            int k0 = kn * 16;
            cp16(&S.Ah[sn][am][ac], aSrcH + k0);
            cp16(&S.Al[sn][am][ac], aSrcL + k0);
            cp16(&S.Bh[sn][brow][bcol], bSrcH + (size_t)k0 * IDIM);
            cp16(&S.Bl[sn][brow][bcol], bSrcL + (size_t)k0 * IDIM);
        }
        cp_commit();

        const int s = kt & (STAGES - 1);
        uint32_t ah[2][4], al[2][4];
#pragma unroll
        for (int mt = 0; mt < 2; mt++) {
            int r = wm * 32 + mt * 16 + (lane & 15);
            int c = (lane >> 4) * 8;
            ldsm4(ah[mt], smaddr(&S.Ah[s][r][c]));
            ldsm4(al[mt], smaddr(&S.Al[s][r][c]));
        }
#pragma unroll
        for (int g = 0; g < 4; g++) {
            int n0 = ((g & 2) ? 64 : 0) + wn * 32 + (g & 1) * 16;
            int bc = n0 + (lane >> 4) * 8;
            int brr = lane & 15;
            uint32_t bh[4], bl[4];
            ldsm4t(bh, smaddr(&S.Bh[s][brr][bc]));
            ldsm4t(bl, smaddr(&S.Bl[s][brr][bc]));
            int j = g * 2;
#pragma unroll
            for (int mt = 0; mt < 2; mt++) {
                mma_bf16(acc[mt][j],     ah[mt], bh);
                mma_bf16(acc[mt][j],     ah[mt], bl);
                mma_bf16(acc[mt][j],     al[mt], bh);
                mma_bf16(acc[mt][j + 1], ah[mt], bh + 2);
                mma_bf16(acc[mt][j + 1], ah[mt], bl + 2);
                mma_bf16(acc[mt][j + 1], al[mt], bh + 2);
            }
        }
    }

    // epilogue: silu(gate)*up -> g_o1h/g_o1l (bf16 hi/lo)
#pragma unroll
    for (int mt = 0; mt < 2; mt++) {
        int r0 = base_m + wm * 32 + mt * 16 + (lane >> 2);
        size_t row0 = (size_t)seg * SEG + r0;
        size_t row1 = row0 + 8;
#pragma unroll
        for (int jg = 0; jg < 4; jg++) {
            float* G = acc[mt][jg];
            float* U = acc[mt][4 + jg];
            int col = nb * 64 + wn * 32 + jg * 8 + (lane & 3) * 2;
            float o0 = U[0] * G[0] / (1.0f + expf(-G[0]));
            float o1 = U[1] * G[1] / (1.0f + expf(-G[1]));
            float o2 = U[2] * G[2] / (1.0f + expf(-G[2]));
            float o3 = U[3] * G[3] / (1.0f + expf(-G[3]));
            uint32_t h01, l01, h23, l23;
            split2(o0, o1, h01, l01);
            split2(o2, o3, h23, l23);
            *(uint32_t*)&g_o1h[row0 * IDIM + col] = h01;
            *(uint32_t*)&g_o1l[row0 * IDIM + col] = l01;
            *(uint32_t*)&g_o1h[row1 * IDIM + col] = h23;
            *(uint32_t*)&g_o1l[row1 * IDIM + col] = l23;
        }
    }
}

// ---------------------------------------------------------------------------
// GEMM2: g_o1 @ down_w, weight-scaled atomic scatter. Same pipeline.
// ---------------------------------------------------------------------------
__global__ __launch_bounds__(256, 2) void gemm2_kernel(float* __restrict__ out)
{
    const int seg = blockIdx.y >> 5;
    const int base_m = (blockIdx.y & 31) * 128;
    const __nv_bfloat16 *bwh, *bwl;
    if (seg < NEXP) {
        if (base_m >= g_cnt[seg]) return;
        size_t off = (size_t)seg * IDIM * HDIM;
        bwh = g_dwh + off; bwl = g_dwl + off;
    } else { bwh = g_sdwh; bwl = g_sdwl; }

    extern __shared__ char smem_raw[];
    G2Smem& S = *(G2Smem*)smem_raw;

    const int tid = threadIdx.x;
    const int lane = tid & 31, wid = tid >> 5;
    const int wm = wid & 3, wn = wid >> 2;
    const int nb = blockIdx.x;

    if (tid < 128) {
        if (seg < NEXP) {
            S.tok[tid] = g_row_token[seg * SEG + base_m + tid];
            S.w[tid]   = g_row_weight[seg * SEG + base_m + tid];
        } else { S.tok[tid] = base_m + tid; S.w[tid] = 1.0f; }
    }
    __syncthreads();

    const int am = tid >> 1, ac = (tid & 1) * 8;
    const size_t arow = ((size_t)seg * SEG + base_m + am) * IDIM + ac;
    const __nv_bfloat16* aSrcH = g_o1h + arow;
    const __nv_bfloat16* aSrcL = g_o1l + arow;
    const int brow = tid >> 4, bcol = (tid & 15) * 8;
    const size_t boff = (size_t)brow * HDIM + nb * 128 + bcol;
    const __nv_bfloat16* bSrcH = bwh + boff;
    const __nv_bfloat16* bSrcL = bwl + boff;

    float acc[2][8][4];
#pragma unroll
    for (int i = 0; i < 2; i++)
#pragma unroll
        for (int j = 0; j < 8; j++)
#pragma unroll
            for (int q = 0; q < 4; q++) acc[i][j][q] = 0.0f;

    const int KSTEPS = IDIM / 16;   // 128
#pragma unroll 1
    for (int s = 0; s < STAGES - 1; s++) {
        int k0 = s * 16;
        cp16(&S.Ah[s][am][ac], aSrcH + k0);
        cp16(&S.Al[s][am][ac], aSrcL + k0);
        cp16(&S.Bh[s][brow][bcol], bSrcH + (size_t)k0 * HDIM);
        cp16(&S.Bl[s][brow][bcol], bSrcL + (size_t)k0 * HDIM);
        cp_commit();
    }

#pragma unroll 1
    for (int kt = 0; kt < KSTEPS; kt++) {
        cp_wait<STAGES - 2>();
        __syncthreads();

        int kn = kt + STAGES - 1;
        if (kn < KSTEPS) {
            int sn = kn & (STAGES - 1);
            int k0 = kn * 16;
            cp16(&S.Ah[sn][am][ac], aSrcH + k0);
            cp16(&S.Al[sn][am][ac], aSrcL + k0);
            cp16(&S.Bh[sn][brow][bcol], bSrcH + (size_t)k0 * HDIM);
            cp16(&S.Bl[sn][brow][bcol], bSrcL + (size_t)k0 * HDIM);
        }
        cp_commit();

        const int s = kt & (STAGES - 1);
        uint32_t ah[2][4], al[2][4];
#pragma unroll
        for (int mt = 0; mt < 2; mt++) {
            int r = wm * 32 + mt * 16 + (lane & 15);
            int c = (lane >> 4) * 8;
            ldsm4(ah[mt], smaddr(&S.Ah[s][r][c]));
            ldsm4(al[mt], smaddr(&S.Al[s][r][c]));
        }
#pragma unroll
        for (int g = 0; g < 4; g++) {
            int n0 = wn * 64 + g * 16;
            int bc = n0 + (lane >> 4) * 8;
            int brr = lane & 15;
            uint32_t bh[4], bl[4];
            ldsm4t(bh, smaddr(&S.Bh[s][brr][bc]));
            ldsm4t(bl, smaddr(&S.Bl[s][brr][bc]));
            int j = g * 2;
#pragma unroll
            for (int mt = 0; mt < 2; mt++) {
                mma_bf16(acc[mt][j],     ah[mt], bh);
                mma_bf16(acc[mt][j],     ah[mt], bl);
                mma_bf16(acc[mt][j],     al[mt], bh);
                mma_bf16(acc[mt][j + 1], ah[mt], bh + 2);
                mma_bf16(acc[mt][j + 1], ah[mt], bl + 2);
                mma_bf16(acc[mt][j + 1], al[mt], bh + 2);
            }
        }
    }

    // epilogue: weight-scaled scatter-add
#pragma unroll
    for (int mt = 0; mt < 2; mt++) {
        int rl0 = wm * 32 + mt * 16 + (lane >> 2);
        int t0 = S.tok[rl0], t1 = S.tok[rl0 + 8];
        float w0 = S.w[rl0], w1 = S.w[rl0 + 8];
#pragma unroll
        for (int j = 0; j < 8; j++) {
            float* C = acc[mt][j];
            int col = nb * 128 + wn * 64 + j * 8 + (lane & 3) * 2;
            atomicAdd(&out[(size_t)t0 * HDIM + col],     w0 * C[0]);
            atomicAdd(&out[(size_t)t0 * HDIM + col + 1], w0 * C[1]);
            atomicAdd(&out[(size_t)t1 * HDIM + col],     w1 * C[2]);
            atomicAdd(&out[(size_t)t1 * HDIM + col + 1], w1 * C[3]);
        }
    }
}

// ---------------------------------------------------------------------------
// Launch
// ---------------------------------------------------------------------------
extern "C" void kernel_launch(void* const* d_in, const int* in_sizes, int n_in,
                              void* d_out, int out_size) {
    (void)in_sizes; (void)n_in; (void)out_size;
    const float* x   = (const float*)d_in[0];
    const float* rw  = (const float*)d_in[1];
    const float* gw  = (const float*)d_in[2];
    const float* uw  = (const float*)d_in[3];
    const float* dw  = (const float*)d_in[4];
    const float* sgw = (const float*)d_in[5];
    const float* suw = (const float*)d_in[6];
    const float* sdw = (const float*)d_in[7];
    float* out = (float*)d_out;

    cudaFuncSetAttribute(gemm1_kernel,
        cudaFuncAttributeMaxDynamicSharedMemorySize, (int)sizeof(G1Smem));
    cudaFuncSetAttribute(gemm2_kernel,
        cudaFuncAttributeMaxDynamicSharedMemorySize, (int)sizeof(G2Smem));

    cudaMemsetAsync(d_out, 0, (size_t)NTOK * HDIM * sizeof(float));
    init_kernel<<<64, 256>>>();
    convert_kernel<<<dim3(2048, 7), 256>>>(x, gw, uw, dw, sgw, suw, sdw);
    router_kernel<<<NTOK / 8, 256>>>(x, rw, out);
    finalize_kernel<<<1, 32>>>(out);

    dim3 g1(IDIM / 64, NSEG * 32);      // (32, 288)
    gemm1_kernel<<<g1, 256, sizeof(G1Smem)>>>();

    dim3 g2(HDIM / 128, NSEG * 32);     // (8, 288)
    gemm2_kernel<<<g2, 256, sizeof(G2Smem)>>>(out);
}